// round 1
// baseline (speedup 1.0000x reference)
#include <cuda_runtime.h>
#include <cuda_bf16.h>

#define N_NODES 50000
#define N_EDGES 800000
#define IN_DIM  100
#define OUT_DIM 40
#define CH      25           // float4 chunks per feature row (100/4)
#define K_HOPS  3

// ---------------- scratch (device globals: no allocation allowed) ----------
__device__ float4 g_B0[N_NODES * CH];   // current (pre-scaled) features
__device__ float4 g_B1[N_NODES * CH];   // scatter accumulator
__device__ float  g_norm[N_NODES];
__device__ int    g_deg[N_NODES];
__device__ float  g_colsum[IN_DIM];
__device__ float  g_colsq[IN_DIM];
__device__ float  g_Wt[IN_DIM * OUT_DIM];  // normalized, transposed weights [f][o]
__device__ float  g_bn[OUT_DIM];           // folded bias

// ---------------- kernels --------------------------------------------------

// zero degree + column stats
__global__ void k_zero_init() {
    int i = blockIdx.x * blockDim.x + threadIdx.x;
    if (i < N_NODES) g_deg[i] = 0;
    if (i < IN_DIM) { g_colsum[i] = 0.f; g_colsq[i] = 0.f; }
}

// in-degree histogram
__global__ void k_degree(const int* __restrict__ dst) {
    int i = blockIdx.x * blockDim.x + threadIdx.x;
    if (i < N_EDGES) atomicAdd(&g_deg[dst[i]], 1);
}

// norm = max(deg,1)^-0.5
__global__ void k_norm() {
    int i = blockIdx.x * blockDim.x + threadIdx.x;
    if (i < N_NODES) g_norm[i] = rsqrtf(fmaxf((float)g_deg[i], 1.0f));
}

// B0 = feat * norm[row];  B1 = 0
__global__ void k_pre(const float4* __restrict__ feat) {
    int i = blockIdx.x * blockDim.x + threadIdx.x;
    if (i >= N_NODES * CH) return;
    int row = i / CH;
    float n = g_norm[row];
    float4 f = feat[i];
    f.x *= n; f.y *= n; f.z *= n; f.w *= n;
    g_B0[i] = f;
    g_B1[i] = make_float4(0.f, 0.f, 0.f, 0.f);
}

// scatter: B1[dst] += B0[src]   (edge x chunk parallel, vector red)
__global__ void k_scatter(const int* __restrict__ src, const int* __restrict__ dst) {
    int tid = blockIdx.x * blockDim.x + threadIdx.x;
    if (tid >= N_EDGES * CH) return;
    int e = tid / CH;
    int c = tid - e * CH;
    int s = __ldg(&src[e]);
    int d = __ldg(&dst[e]);
    float4 v = g_B0[s * CH + c];
    float4* addr = &g_B1[d * CH + c];
    asm volatile("red.global.add.v4.f32 [%0], {%1,%2,%3,%4};"
                 :: "l"(addr), "f"(v.x), "f"(v.y), "f"(v.z), "f"(v.w) : "memory");
}

// B0 = B1 * norm^2 ; B1 = 0   (between hops: norm[dst] of this hop * norm[src] of next)
__global__ void k_transform() {
    int i = blockIdx.x * blockDim.x + threadIdx.x;
    if (i >= N_NODES * CH) return;
    int row = i / CH;
    float n = g_norm[row];
    float n2 = n * n;
    float4 s = g_B1[i];
    s.x *= n2; s.y *= n2; s.z *= n2; s.w *= n2;
    g_B0[i] = s;
    g_B1[i] = make_float4(0.f, 0.f, 0.f, 0.f);
}

// last hop: B0 = B1 * norm, and accumulate per-column sum / sumsq
// layout: chunk = tid % 25 handles features [4c,4c+4); slots stride over rows.
__global__ void k_finalize_stats(int n_slots_total) {
    __shared__ float ssum[CH][4];
    __shared__ float ssq[CH][4];
    int tid = threadIdx.x;
    if (tid < CH) {
        #pragma unroll
        for (int k = 0; k < 4; k++) { ssum[tid][k] = 0.f; ssq[tid][k] = 0.f; }
    }
    __syncthreads();

    int chunk = tid % CH;
    int slot  = tid / CH;                 // 0..9 for blockDim 256 (threads 250..255 idle)
    float4 psum = make_float4(0, 0, 0, 0);
    float4 psq  = make_float4(0, 0, 0, 0);
    if (slot < 10) {
        int rowslot = blockIdx.x * 10 + slot;
        for (int r = rowslot; r < N_NODES; r += n_slots_total) {
            float n = g_norm[r];
            float4 v = g_B1[r * CH + chunk];
            v.x *= n; v.y *= n; v.z *= n; v.w *= n;
            g_B0[r * CH + chunk] = v;
            psum.x += v.x; psum.y += v.y; psum.z += v.z; psum.w += v.w;
            psq.x += v.x * v.x; psq.y += v.y * v.y; psq.z += v.z * v.z; psq.w += v.w * v.w;
        }
        atomicAdd(&ssum[chunk][0], psum.x); atomicAdd(&ssum[chunk][1], psum.y);
        atomicAdd(&ssum[chunk][2], psum.z); atomicAdd(&ssum[chunk][3], psum.w);
        atomicAdd(&ssq[chunk][0], psq.x);  atomicAdd(&ssq[chunk][1], psq.y);
        atomicAdd(&ssq[chunk][2], psq.z);  atomicAdd(&ssq[chunk][3], psq.w);
    }
    __syncthreads();
    if (tid < CH) {
        #pragma unroll
        for (int k = 0; k < 4; k++) {
            atomicAdd(&g_colsum[tid * 4 + k], ssum[tid][k]);
            atomicAdd(&g_colsq[tid * 4 + k], ssq[tid][k]);
        }
    }
}

// fold standardization into weights: Wt[f][o] = W[o][f]*istd[f];
// bn[o] = b[o] - sum_f mean[f]*istd[f]*W[o][f]
__global__ void k_fold(const float* __restrict__ W, const float* __restrict__ b) {
    __shared__ float s_mean[IN_DIM];
    __shared__ float s_istd[IN_DIM];
    int t = threadIdx.x;
    if (t < IN_DIM) {
        float mean = g_colsum[t] / (float)N_NODES;
        float var = (g_colsq[t] - (float)N_NODES * mean * mean) / (float)(N_NODES - 1);
        float istd = rsqrtf(var);
        s_mean[t] = mean;
        s_istd[t] = istd;
    }
    __syncthreads();
    for (int i = t; i < IN_DIM * OUT_DIM; i += blockDim.x) {
        int o = i / IN_DIM;
        int f = i - o * IN_DIM;
        g_Wt[f * OUT_DIM + o] = W[i] * s_istd[f];
    }
    if (t < OUT_DIM) {
        float acc = b[t];
        for (int f = 0; f < IN_DIM; f++)
            acc -= s_mean[f] * s_istd[f] * W[t * IN_DIM + f];
        g_bn[t] = acc;
    }
}

// out[row] = H[row] @ Wt + bn   (thread per row, W in shared, broadcast LDS)
__global__ void k_gemm(float* __restrict__ out) {
    __shared__ __align__(16) float s_Wt[IN_DIM * OUT_DIM];
    __shared__ float s_bn[OUT_DIM];
    int t = threadIdx.x;
    for (int i = t; i < IN_DIM * OUT_DIM; i += blockDim.x) s_Wt[i] = g_Wt[i];
    if (t < OUT_DIM) s_bn[t] = g_bn[t];
    __syncthreads();

    int row = blockIdx.x * blockDim.x + t;
    if (row >= N_NODES) return;

    float acc[OUT_DIM];
    #pragma unroll
    for (int o = 0; o < OUT_DIM; o++) acc[o] = s_bn[o];

    #pragma unroll
    for (int c = 0; c < CH; c++) {
        float4 h4 = g_B0[row * CH + c];
        #pragma unroll
        for (int k = 0; k < 4; k++) {
            float hv = (k == 0) ? h4.x : (k == 1) ? h4.y : (k == 2) ? h4.z : h4.w;
            const float4* wr = (const float4*)&s_Wt[(c * 4 + k) * OUT_DIM];
            #pragma unroll
            for (int j = 0; j < 10; j++) {
                float4 w = wr[j];
                acc[4 * j + 0] += hv * w.x;
                acc[4 * j + 1] += hv * w.y;
                acc[4 * j + 2] += hv * w.z;
                acc[4 * j + 3] += hv * w.w;
            }
        }
    }
    float4* op = (float4*)(out + (size_t)row * OUT_DIM);
    #pragma unroll
    for (int j = 0; j < 10; j++)
        op[j] = make_float4(acc[4 * j + 0], acc[4 * j + 1], acc[4 * j + 2], acc[4 * j + 3]);
}

// ---------------- launch ----------------------------------------------------

extern "C" void kernel_launch(void* const* d_in, const int* in_sizes, int n_in,
                              void* d_out, int out_size) {
    const float4* feat = (const float4*)d_in[0];   // [N, 100] f32
    const float*  W    = (const float*)d_in[1];    // [40, 100] f32
    const float*  b    = (const float*)d_in[2];    // [40] f32
    const int*    src  = (const int*)d_in[3];      // [E] i32
    const int*    dst  = (const int*)d_in[4];      // [E] i32
    float*        out  = (float*)d_out;            // [N, 40] f32

    const int TB = 256;
    const int n_node_blk   = (N_NODES + TB - 1) / TB;
    const int n_edge_blk   = (N_EDGES + TB - 1) / TB;
    const int n_chunk_blk  = (N_NODES * CH + TB - 1) / TB;
    const int n_scat_blk   = (N_EDGES * CH + TB - 1) / TB;

    k_zero_init<<<n_node_blk, TB>>>();
    k_degree<<<n_edge_blk, TB>>>(dst);
    k_norm<<<n_node_blk, TB>>>();
    k_pre<<<n_chunk_blk, TB>>>(feat);

    for (int hop = 0; hop < K_HOPS; hop++) {
        k_scatter<<<n_scat_blk, TB>>>(src, dst);
        if (hop + 1 < K_HOPS)
            k_transform<<<n_chunk_blk, TB>>>();
    }

    const int STAT_BLKS = 128;                 // 10 row-slots per block
    k_finalize_stats<<<STAT_BLKS, TB>>>(STAT_BLKS * 10);
    k_fold<<<1, 128>>>(W, b);
    k_gemm<<<n_node_blk, TB>>>(out);
}

// round 3
// speedup vs baseline: 2.6642x; 2.6642x over previous
#include <cuda_runtime.h>
#include <cuda_bf16.h>

#define N_NODES 50000
#define N_EDGES 800000
#define IN_DIM  100
#define OUT_DIM 40
#define CH      25           // float4 chunks per feature row (100/4)
#define SCAN_B  256
#define NSB     196          // ceil(50000/256)
#define NODES_PER_BLK 10     // 250 active threads of 256

// ---------------- scratch (device globals: no allocation allowed) ----------
__device__ float4 g_B0[N_NODES * CH];
__device__ float4 g_B1[N_NODES * CH];
__device__ float  g_norm[N_NODES];
__device__ int    g_deg[N_NODES];
__device__ int    g_rowptr[N_NODES + 1];
__device__ int    g_pos[N_NODES];
__device__ int    g_bsum[NSB];
__device__ int    g_esrc[N_EDGES];
__device__ float  g_colsum[IN_DIM];
__device__ float  g_colsq[IN_DIM];
__device__ float  g_Wt[IN_DIM * OUT_DIM];
__device__ float  g_bn[OUT_DIM];

// ---------------- setup kernels --------------------------------------------

__global__ void k_zero() {
    int i = blockIdx.x * blockDim.x + threadIdx.x;
    if (i < N_NODES) g_deg[i] = 0;
    if (i < IN_DIM) { g_colsum[i] = 0.f; g_colsq[i] = 0.f; }
}

__global__ void k_degree(const int* __restrict__ dst) {
    int i = blockIdx.x * blockDim.x + threadIdx.x;
    if (i < N_EDGES) atomicAdd(&g_deg[dst[i]], 1);
}

__global__ void k_norm() {
    int i = blockIdx.x * blockDim.x + threadIdx.x;
    if (i < N_NODES) g_norm[i] = rsqrtf(fmaxf((float)g_deg[i], 1.0f));
}

// ---- 3-phase exclusive scan of degrees -> rowptr ----
__global__ void k_scan1() {
    __shared__ int sh[SCAN_B];
    int t = threadIdx.x;
    int i = blockIdx.x * SCAN_B + t;
    int v = (i < N_NODES) ? g_deg[i] : 0;
    sh[t] = v;
    __syncthreads();
    #pragma unroll
    for (int off = 1; off < SCAN_B; off <<= 1) {
        int x = (t >= off) ? sh[t - off] : 0;
        __syncthreads();
        sh[t] += x;
        __syncthreads();
    }
    if (i < N_NODES) g_rowptr[i + 1] = sh[t];   // local inclusive (patched in scan3)
    if (t == SCAN_B - 1) g_bsum[blockIdx.x] = sh[t];
    if (i == 0) g_rowptr[0] = 0;
}

__global__ void k_scan2() {   // 1 block, exclusive scan of NSB block sums
    __shared__ int sh[SCAN_B];
    int t = threadIdx.x;
    int v = (t < NSB) ? g_bsum[t] : 0;
    sh[t] = v;
    __syncthreads();
    #pragma unroll
    for (int off = 1; off < SCAN_B; off <<= 1) {
        int x = (t >= off) ? sh[t - off] : 0;
        __syncthreads();
        sh[t] += x;
        __syncthreads();
    }
    if (t < NSB) g_bsum[t] = sh[t] - v;         // exclusive
}

__global__ void k_scan3() {
    int i = blockIdx.x * SCAN_B + threadIdx.x;
    if (i < N_NODES) g_rowptr[i + 1] += g_bsum[blockIdx.x];
}

__global__ void k_pos() {
    int i = blockIdx.x * blockDim.x + threadIdx.x;
    if (i < N_NODES) g_pos[i] = g_rowptr[i];
}

__global__ void k_fill(const int* __restrict__ src, const int* __restrict__ dst) {
    int i = blockIdx.x * blockDim.x + threadIdx.x;
    if (i < N_EDGES) {
        int slot = atomicAdd(&g_pos[dst[i]], 1);
        g_esrc[slot] = src[i];
    }
}

// ---------------- pull SpMM -------------------------------------------------
// Buffer ids resolved DEVICE-side (host code must never take &g_B0!).
// IN:  0 = feat (kernel arg), 1 = g_B0, 2 = g_B1
// OUT: 1 = g_B0, 2 = g_B1
// MODE 0: scale gathered rows by norm[src], epilogue *= norm[v]^2
// MODE 1: epilogue *= norm[v]^2
// MODE 2: epilogue *= norm[v]   (final hop)
template <int MODE, int IN, int OUT>
__global__ void k_spmm(const float4* __restrict__ feat) {
    const float4* __restrict__ in = (IN == 0) ? feat : (IN == 1) ? g_B0 : g_B1;
    float4* __restrict__ out = (OUT == 1) ? g_B0 : g_B1;

    int t = threadIdx.x;
    if (t >= NODES_PER_BLK * CH) return;
    int local = t / CH;
    int c = t - local * CH;
    int node = blockIdx.x * NODES_PER_BLK + local;
    if (node >= N_NODES) return;

    int beg = __ldg(&g_rowptr[node]);
    int end = __ldg(&g_rowptr[node + 1]);

    float ax = 0.f, ay = 0.f, az = 0.f, aw = 0.f;
    for (int e = beg; e < end; e++) {
        int s = __ldg(&g_esrc[e]);
        float4 v = __ldg(&in[s * CH + c]);
        if (MODE == 0) {
            float ns = __ldg(&g_norm[s]);
            v.x *= ns; v.y *= ns; v.z *= ns; v.w *= ns;
        }
        ax += v.x; ay += v.y; az += v.z; aw += v.w;
    }
    float n = __ldg(&g_norm[node]);
    float f = (MODE == 2) ? n : n * n;
    out[node * CH + c] = make_float4(ax * f, ay * f, az * f, aw * f);
}

// ---------------- column stats over final H (g_B0) --------------------------
__global__ void k_stats(int n_slots_total) {
    __shared__ float ssum[CH][4];
    __shared__ float ssq[CH][4];
    int tid = threadIdx.x;
    if (tid < CH) {
        #pragma unroll
        for (int k = 0; k < 4; k++) { ssum[tid][k] = 0.f; ssq[tid][k] = 0.f; }
    }
    __syncthreads();

    int chunk = tid % CH;
    int slot  = tid / CH;
    float4 psum = make_float4(0, 0, 0, 0);
    float4 psq  = make_float4(0, 0, 0, 0);
    if (slot < NODES_PER_BLK) {
        int rowslot = blockIdx.x * NODES_PER_BLK + slot;
        for (int r = rowslot; r < N_NODES; r += n_slots_total) {
            float4 v = g_B0[r * CH + chunk];
            psum.x += v.x; psum.y += v.y; psum.z += v.z; psum.w += v.w;
            psq.x += v.x * v.x; psq.y += v.y * v.y; psq.z += v.z * v.z; psq.w += v.w * v.w;
        }
        atomicAdd(&ssum[chunk][0], psum.x); atomicAdd(&ssum[chunk][1], psum.y);
        atomicAdd(&ssum[chunk][2], psum.z); atomicAdd(&ssum[chunk][3], psum.w);
        atomicAdd(&ssq[chunk][0], psq.x);  atomicAdd(&ssq[chunk][1], psq.y);
        atomicAdd(&ssq[chunk][2], psq.z);  atomicAdd(&ssq[chunk][3], psq.w);
    }
    __syncthreads();
    if (tid < CH) {
        #pragma unroll
        for (int k = 0; k < 4; k++) {
            atomicAdd(&g_colsum[tid * 4 + k], ssum[tid][k]);
            atomicAdd(&g_colsq[tid * 4 + k], ssq[tid][k]);
        }
    }
}

// fold standardization into weights
__global__ void k_fold(const float* __restrict__ W, const float* __restrict__ b) {
    __shared__ float s_mean[IN_DIM];
    __shared__ float s_istd[IN_DIM];
    int t = threadIdx.x;
    if (t < IN_DIM) {
        float mean = g_colsum[t] / (float)N_NODES;
        float var = (g_colsq[t] - (float)N_NODES * mean * mean) / (float)(N_NODES - 1);
        float istd = rsqrtf(var);
        s_mean[t] = mean;
        s_istd[t] = istd;
    }
    __syncthreads();
    for (int i = t; i < IN_DIM * OUT_DIM; i += blockDim.x) {
        int o = i / IN_DIM;
        int f = i - o * IN_DIM;
        g_Wt[f * OUT_DIM + o] = W[i] * s_istd[f];
    }
    if (t < OUT_DIM) {
        float acc = b[t];
        for (int f = 0; f < IN_DIM; f++)
            acc -= s_mean[f] * s_istd[f] * W[t * IN_DIM + f];
        g_bn[t] = acc;
    }
}

// out[row] = H[row] @ Wt + bn
__global__ void k_gemm(float* __restrict__ out) {
    __shared__ __align__(16) float s_Wt[IN_DIM * OUT_DIM];
    __shared__ float s_bn[OUT_DIM];
    int t = threadIdx.x;
    for (int i = t; i < IN_DIM * OUT_DIM; i += blockDim.x) s_Wt[i] = g_Wt[i];
    if (t < OUT_DIM) s_bn[t] = g_bn[t];
    __syncthreads();

    int row = blockIdx.x * blockDim.x + t;
    if (row >= N_NODES) return;

    float acc[OUT_DIM];
    #pragma unroll
    for (int o = 0; o < OUT_DIM; o++) acc[o] = s_bn[o];

    #pragma unroll
    for (int c = 0; c < CH; c++) {
        float4 h4 = g_B0[row * CH + c];
        #pragma unroll
        for (int k = 0; k < 4; k++) {
            float hv = (k == 0) ? h4.x : (k == 1) ? h4.y : (k == 2) ? h4.z : h4.w;
            const float4* wr = (const float4*)&s_Wt[(c * 4 + k) * OUT_DIM];
            #pragma unroll
            for (int j = 0; j < 10; j++) {
                float4 w = wr[j];
                acc[4 * j + 0] += hv * w.x;
                acc[4 * j + 1] += hv * w.y;
                acc[4 * j + 2] += hv * w.z;
                acc[4 * j + 3] += hv * w.w;
            }
        }
    }
    float4* op = (float4*)(out + (size_t)row * OUT_DIM);
    #pragma unroll
    for (int j = 0; j < 10; j++)
        op[j] = make_float4(acc[4 * j + 0], acc[4 * j + 1], acc[4 * j + 2], acc[4 * j + 3]);
}

// ---------------- launch ----------------------------------------------------

extern "C" void kernel_launch(void* const* d_in, const int* in_sizes, int n_in,
                              void* d_out, int out_size) {
    const float4* feat = (const float4*)d_in[0];   // [N, 100] f32
    const float*  W    = (const float*)d_in[1];    // [40, 100] f32
    const float*  b    = (const float*)d_in[2];    // [40] f32
    const int*    src  = (const int*)d_in[3];      // [E] i32
    const int*    dst  = (const int*)d_in[4];      // [E] i32
    float*        out  = (float*)d_out;            // [N, 40] f32

    const int TB = 256;
    const int n_node_blk = (N_NODES + TB - 1) / TB;
    const int n_edge_blk = (N_EDGES + TB - 1) / TB;
    const int n_spmm_blk = (N_NODES + NODES_PER_BLK - 1) / NODES_PER_BLK;

    // CSR build
    k_zero<<<n_node_blk, TB>>>();
    k_degree<<<n_edge_blk, TB>>>(dst);
    k_norm<<<n_node_blk, TB>>>();
    k_scan1<<<NSB, SCAN_B>>>();
    k_scan2<<<1, SCAN_B>>>();
    k_scan3<<<NSB, SCAN_B>>>();
    k_pos<<<n_node_blk, TB>>>();
    k_fill<<<n_edge_blk, TB>>>(src, dst);

    // 3 hops, pull-based (atomic-free); buffers selected device-side
    k_spmm<0, 0, 1><<<n_spmm_blk, TB>>>(feat);   // feat -> B0
    k_spmm<1, 1, 2><<<n_spmm_blk, TB>>>(feat);   // B0 -> B1
    k_spmm<2, 2, 1><<<n_spmm_blk, TB>>>(feat);   // B1 -> B0

    // standardize + classify
    const int STAT_BLKS = 128;
    k_stats<<<STAT_BLKS, TB>>>(STAT_BLKS * NODES_PER_BLK);
    k_fold<<<1, 128>>>(W, b);
    k_gemm<<<n_node_blk, TB>>>(out);
}

// round 4
// speedup vs baseline: 3.1214x; 1.1716x over previous
#include <cuda_runtime.h>
#include <cuda_fp16.h>

#define N_NODES 50000
#define N_EDGES 800000
#define IN_DIM  100
#define OUT_DIM 40
#define CH      25           // 4-feature chunks per row (100/4)
#define SCAN_B  256
#define NSB     196          // ceil(50000/256)
#define NODES_PER_BLK 10     // 250 active threads of 256

// ---------------- scratch (device globals) ----------------------------------
__device__ float4 g_B0[N_NODES * CH];          // final H (fp32)
__device__ uint2  g_P[N_NODES * CH];           // fp16 ping
__device__ uint2  g_Q[N_NODES * CH];           // fp16 pong
__device__ float  g_norm[N_NODES];
__device__ int    g_deg[N_NODES];
__device__ int    g_rowptr[N_NODES + 1];
__device__ int    g_pos[N_NODES];
__device__ int    g_bsum[NSB];
__device__ int    g_esrc[N_EDGES];
__device__ float  g_colsum[IN_DIM];
__device__ float  g_colsq[IN_DIM];

// ---------------- setup ------------------------------------------------------

__global__ void k_zero() {
    int i = blockIdx.x * blockDim.x + threadIdx.x;
    if (i < N_NODES) g_deg[i] = 0;
    if (i < IN_DIM) { g_colsum[i] = 0.f; g_colsq[i] = 0.f; }
}

__global__ void k_degree(const int* __restrict__ dst) {
    int i = blockIdx.x * blockDim.x + threadIdx.x;
    if (i < N_EDGES) atomicAdd(&g_deg[dst[i]], 1);
}

// warp-shuffle block scan: rowptr[i+1] = block-local inclusive; bsum = block total
__global__ void k_scan1() {
    int t = threadIdx.x;
    int i = blockIdx.x * SCAN_B + t;
    int v = (i < N_NODES) ? g_deg[i] : 0;
    int lane = t & 31, w = t >> 5;
    int x = v;
    #pragma unroll
    for (int off = 1; off < 32; off <<= 1) {
        int y = __shfl_up_sync(0xffffffffu, x, off);
        if (lane >= off) x += y;
    }
    __shared__ int wsum[8];
    if (lane == 31) wsum[w] = x;
    __syncthreads();
    if (w == 0) {
        int s = (lane < 8) ? wsum[lane] : 0;
        #pragma unroll
        for (int off = 1; off < 8; off <<= 1) {
            int y = __shfl_up_sync(0xffffffffu, s, off);
            if (lane >= off) s += y;
        }
        if (lane < 8) wsum[lane] = s;
    }
    __syncthreads();
    int incl = x + (w > 0 ? wsum[w - 1] : 0);
    if (i < N_NODES) g_rowptr[i + 1] = incl;
    if (t == SCAN_B - 1) g_bsum[blockIdx.x] = incl;
    if (i == 0) g_rowptr[0] = 0;
}

__global__ void k_scan2() {   // exclusive scan of NSB block sums (1 block)
    int t = threadIdx.x;
    int v = (t < NSB) ? g_bsum[t] : 0;
    int lane = t & 31, w = t >> 5;
    int x = v;
    #pragma unroll
    for (int off = 1; off < 32; off <<= 1) {
        int y = __shfl_up_sync(0xffffffffu, x, off);
        if (lane >= off) x += y;
    }
    __shared__ int wsum[8];
    if (lane == 31) wsum[w] = x;
    __syncthreads();
    if (w == 0) {
        int s = (lane < 8) ? wsum[lane] : 0;
        #pragma unroll
        for (int off = 1; off < 8; off <<= 1) {
            int y = __shfl_up_sync(0xffffffffu, s, off);
            if (lane >= off) s += y;
        }
        if (lane < 8) wsum[lane] = s;
    }
    __syncthreads();
    int incl = x + (w > 0 ? wsum[w - 1] : 0);
    if (t < NSB) g_bsum[t] = incl - v;   // exclusive
}

// finalize rowptr, derive pos + norm in one pass
__global__ void k_scan3np() {
    int i = blockIdx.x * SCAN_B + threadIdx.x;
    if (i >= N_NODES) return;
    int incl = g_rowptr[i + 1] + g_bsum[blockIdx.x];
    g_rowptr[i + 1] = incl;
    int d = g_deg[i];
    g_pos[i] = incl - d;                 // = final rowptr[i]
    g_norm[i] = rsqrtf(fmaxf((float)d, 1.0f));
}

__global__ void k_fill(const int* __restrict__ src, const int* __restrict__ dst) {
    int i = blockIdx.x * blockDim.x + threadIdx.x;
    if (i < N_EDGES) {
        int slot = atomicAdd(&g_pos[dst[i]], 1);
        g_esrc[slot] = src[i];
    }
}

// P = fp16(feat * norm[row])
__global__ void k_pre16(const float4* __restrict__ feat) {
    int i = blockIdx.x * blockDim.x + threadIdx.x;
    if (i >= N_NODES * CH) return;
    int row = i / CH;
    float n = __ldg(&g_norm[row]);
    float4 f = __ldg(&feat[i]);
    half2 a = __floats2half2_rn(f.x * n, f.y * n);
    half2 b = __floats2half2_rn(f.z * n, f.w * n);
    uint2 o;
    o.x = *(unsigned*)&a;
    o.y = *(unsigned*)&b;
    g_P[i] = o;
}

// ---------------- pull SpMM (fp16 gather, fp32 accumulate) -------------------
// MODE 1: P -> Q, epilogue norm^2, fp16 out
// MODE 2: Q -> P, epilogue norm^2, fp16 out
// MODE 3: P -> g_B0, epilogue norm, fp32 out
template <int MODE>
__global__ void k_spmm16() {
    const uint2* __restrict__ in = (MODE == 2) ? g_Q : g_P;

    int t = threadIdx.x;
    if (t >= NODES_PER_BLK * CH) return;
    int local = t / CH;
    int c = t - local * CH;
    int node = blockIdx.x * NODES_PER_BLK + local;
    if (node >= N_NODES) return;

    int beg = __ldg(&g_rowptr[node]);
    int end = __ldg(&g_rowptr[node + 1]);

    float ax = 0.f, ay = 0.f, az = 0.f, aw = 0.f;
    int e = beg;
    for (; e + 1 < end; e += 2) {
        int s0 = __ldg(&g_esrc[e]);
        int s1 = __ldg(&g_esrc[e + 1]);
        uint2 r0 = __ldg(&in[s0 * CH + c]);
        uint2 r1 = __ldg(&in[s1 * CH + c]);
        float2 a0 = __half22float2(*(half2*)&r0.x);
        float2 b0 = __half22float2(*(half2*)&r0.y);
        float2 a1 = __half22float2(*(half2*)&r1.x);
        float2 b1 = __half22float2(*(half2*)&r1.y);
        ax += a0.x + a1.x; ay += a0.y + a1.y;
        az += b0.x + b1.x; aw += b0.y + b1.y;
    }
    if (e < end) {
        int s = __ldg(&g_esrc[e]);
        uint2 r = __ldg(&in[s * CH + c]);
        float2 a = __half22float2(*(half2*)&r.x);
        float2 b = __half22float2(*(half2*)&r.y);
        ax += a.x; ay += a.y; az += b.x; aw += b.y;
    }

    float n = __ldg(&g_norm[node]);
    if (MODE == 3) {
        g_B0[node * CH + c] = make_float4(ax * n, ay * n, az * n, aw * n);
    } else {
        float f = n * n;
        half2 h0 = __floats2half2_rn(ax * f, ay * f);
        half2 h1 = __floats2half2_rn(az * f, aw * f);
        uint2 o;
        o.x = *(unsigned*)&h0;
        o.y = *(unsigned*)&h1;
        float4* dummy; (void)dummy;
        ((MODE == 1) ? g_Q : g_P)[node * CH + c] = o;
    }
}

// ---------------- column stats over final H (g_B0) ---------------------------
__global__ void k_stats(int n_slots_total) {
    __shared__ float ssum[CH][4];
    __shared__ float ssq[CH][4];
    int tid = threadIdx.x;
    if (tid < CH) {
        #pragma unroll
        for (int k = 0; k < 4; k++) { ssum[tid][k] = 0.f; ssq[tid][k] = 0.f; }
    }
    __syncthreads();

    int chunk = tid % CH;
    int slot  = tid / CH;
    float4 psum = make_float4(0, 0, 0, 0);
    float4 psq  = make_float4(0, 0, 0, 0);
    if (slot < NODES_PER_BLK) {
        int rowslot = blockIdx.x * NODES_PER_BLK + slot;
        for (int r = rowslot; r < N_NODES; r += n_slots_total) {
            float4 v = g_B0[r * CH + chunk];
            psum.x += v.x; psum.y += v.y; psum.z += v.z; psum.w += v.w;
            psq.x += v.x * v.x; psq.y += v.y * v.y; psq.z += v.z * v.z; psq.w += v.w * v.w;
        }
        atomicAdd(&ssum[chunk][0], psum.x); atomicAdd(&ssum[chunk][1], psum.y);
        atomicAdd(&ssum[chunk][2], psum.z); atomicAdd(&ssum[chunk][3], psum.w);
        atomicAdd(&ssq[chunk][0], psq.x);  atomicAdd(&ssq[chunk][1], psq.y);
        atomicAdd(&ssq[chunk][2], psq.z);  atomicAdd(&ssq[chunk][3], psq.w);
    }
    __syncthreads();
    if (tid < CH) {
        #pragma unroll
        for (int k = 0; k < 4; k++) {
            atomicAdd(&g_colsum[tid * 4 + k], ssum[tid][k]);
            atomicAdd(&g_colsq[tid * 4 + k], ssq[tid][k]);
        }
    }
}

// ---------------- fused fold + GEMM ------------------------------------------
// Each block: recompute mean/istd, build normalized Wt + bias in shared, then
// one row per thread: out[row] = H[row] @ Wt + bn
__global__ void k_gemm_fold(const float* __restrict__ W, const float* __restrict__ b,
                            float* __restrict__ out) {
    __shared__ float s_mean[IN_DIM];
    __shared__ float s_istd[IN_DIM];
    __shared__ __align__(16) float s_Wt[IN_DIM * OUT_DIM];
    __shared__ float s_bn[OUT_DIM];
    int t = threadIdx.x;

    if (t < IN_DIM) {
        float mean = g_colsum[t] / (float)N_NODES;
        float var = (g_colsq[t] - (float)N_NODES * mean * mean) / (float)(N_NODES - 1);
        s_mean[t] = mean;
        s_istd[t] = rsqrtf(var);
    }
    __syncthreads();
    for (int i = t; i < IN_DIM * OUT_DIM; i += blockDim.x) {
        int o = i / IN_DIM;
        int f = i - o * IN_DIM;
        s_Wt[f * OUT_DIM + o] = __ldg(&W[i]) * s_istd[f];
    }
    if (t < OUT_DIM) {
        float acc = __ldg(&b[t]);
        for (int f = 0; f < IN_DIM; f++)
            acc -= s_mean[f] * s_istd[f] * __ldg(&W[t * IN_DIM + f]);
        s_bn[t] = acc;
    }
    __syncthreads();

    int row = blockIdx.x * blockDim.x + t;
    if (row >= N_NODES) return;

    float acc[OUT_DIM];
    #pragma unroll
    for (int o = 0; o < OUT_DIM; o++) acc[o] = s_bn[o];

    #pragma unroll
    for (int c = 0; c < CH; c++) {
        float4 h4 = g_B0[row * CH + c];
        #pragma unroll
        for (int k = 0; k < 4; k++) {
            float hv = (k == 0) ? h4.x : (k == 1) ? h4.y : (k == 2) ? h4.z : h4.w;
            const float4* wr = (const float4*)&s_Wt[(c * 4 + k) * OUT_DIM];
            #pragma unroll
            for (int j = 0; j < 10; j++) {
                float4 w = wr[j];
                acc[4 * j + 0] += hv * w.x;
                acc[4 * j + 1] += hv * w.y;
                acc[4 * j + 2] += hv * w.z;
                acc[4 * j + 3] += hv * w.w;
            }
        }
    }
    float4* op = (float4*)(out + (size_t)row * OUT_DIM);
    #pragma unroll
    for (int j = 0; j < 10; j++)
        op[j] = make_float4(acc[4 * j + 0], acc[4 * j + 1], acc[4 * j + 2], acc[4 * j + 3]);
}

// ---------------- launch ------------------------------------------------------

extern "C" void kernel_launch(void* const* d_in, const int* in_sizes, int n_in,
                              void* d_out, int out_size) {
    const float4* feat = (const float4*)d_in[0];   // [N, 100] f32
    const float*  W    = (const float*)d_in[1];    // [40, 100] f32
    const float*  b    = (const float*)d_in[2];    // [40] f32
    const int*    src  = (const int*)d_in[3];      // [E] i32
    const int*    dst  = (const int*)d_in[4];      // [E] i32
    float*        out  = (float*)d_out;            // [N, 40] f32

    const int TB = 256;
    const int n_node_blk  = (N_NODES + TB - 1) / TB;
    const int n_edge_blk  = (N_EDGES + TB - 1) / TB;
    const int n_chunk_blk = (N_NODES * CH + TB - 1) / TB;
    const int n_spmm_blk  = (N_NODES + NODES_PER_BLK - 1) / NODES_PER_BLK;

    // CSR build
    k_zero<<<n_node_blk, TB>>>();
    k_degree<<<n_edge_blk, TB>>>(dst);
    k_scan1<<<NSB, SCAN_B>>>();
    k_scan2<<<1, SCAN_B>>>();
    k_scan3np<<<NSB, SCAN_B>>>();
    k_fill<<<n_edge_blk, TB>>>(src, dst);

    // fp16 pre-scale + 3 atomic-free fp16-gather hops
    k_pre16<<<n_chunk_blk, TB>>>(feat);
    k_spmm16<1><<<n_spmm_blk, TB>>>();   // P -> Q
    k_spmm16<2><<<n_spmm_blk, TB>>>();   // Q -> P
    k_spmm16<3><<<n_spmm_blk, TB>>>();   // P -> B0 (fp32)

    // standardize + classify
    const int STAT_BLKS = 128;
    k_stats<<<STAT_BLKS, TB>>>(STAT_BLKS * NODES_PER_BLK);
    k_gemm_fold<<<n_node_blk, TB>>>(W, b, out);
}